// round 5
// baseline (speedup 1.0000x reference)
#include <cuda_runtime.h>
#include <cstdint>
#include <cstddef>

// Problem-shape capacities (fixed by the dataset)
#define NODES_CAP 50000
#define EDGES_CAP 800000

// ---------------- device scratch (static: allocation rules) ----------------
__device__ float g_qkv[(size_t)NODES_CAP * 384];   // [N][384] : q|k|v
__device__ float g_s  [(size_t)NODES_CAP * 8];     // [N][8]   : softmax denom
__device__ float g_acc[(size_t)NODES_CAP * 128];   // [N][128] : UNNORMALIZED attn out
__device__ int   g_idx[(size_t)EDGES_CAP * 2];     // row | col as int32
__device__ int   g_idx64;                          // 1 if edge_index is int64

// ---------------------------------------------------------------------------
// Index dtype detection + normalization (JAX may emit int32 despite int64 in
// the reference). Convert to flat int32 either way.
// ---------------------------------------------------------------------------
__global__ void detect_idx(const void* __restrict__ ei, int E, int N)
{
    if (blockIdx.x == 0 && threadIdx.x == 0) {
        const long long* p = (const long long*)ei;
        int ok = 1;
        for (int i = 0; i < 64; i++) {
            const long long v = p[i];
            if (v < 0 || v >= (long long)N) { ok = 0; break; }
        }
        g_idx64 = ok;
    }
}

__global__ __launch_bounds__(256) void convert_idx(const void* __restrict__ ei, int total)
{
    const int t = blockIdx.x * 256 + threadIdx.x;
    if (t >= total) return;
    if (g_idx64) g_idx[t] = (int)((const long long*)ei)[t];
    else         g_idx[t] = ((const int*)ei)[t];
}

__global__ __launch_bounds__(256) void zero_bufs(int N)
{
    const int t = blockIdx.x * 256 + threadIdx.x;
    const int n_s   = N * 8 / 4;
    const int n_acc = N * 128 / 4;
    if (t < n_s)   ((float4*)g_s)[t]   = make_float4(0.f, 0.f, 0.f, 0.f);
    if (t < n_acc) ((float4*)g_acc)[t] = make_float4(0.f, 0.f, 0.f, 0.f);
}

// ---------------------------------------------------------------------------
// Merged QKV SGEMM (NT): blockIdx.x in {0,1,2} selects (Wq|Wk|Wv).
// C[m, 128*bx + n] = sum_k x[m,k] * W[n,k] + b[n].  BM=BN=128, BK=16.
// ---------------------------------------------------------------------------
__global__ __launch_bounds__(256) void sgemm_qkv(
    const float* __restrict__ A,
    const float* __restrict__ Wq, const float* __restrict__ Wk, const float* __restrict__ Wv,
    const float* __restrict__ bq, const float* __restrict__ bk, const float* __restrict__ bv,
    float* __restrict__ C, int M)
{
    __shared__ float As[16][132];
    __shared__ float Bs[16][132];

    const float* B    = (blockIdx.x == 0) ? Wq : (blockIdx.x == 1) ? Wk : Wv;
    const float* bias = (blockIdx.x == 0) ? bq : (blockIdx.x == 1) ? bk : bv;
    const int coff = blockIdx.x << 7;
    const int K = 256, ldc = 384;

    const int tid = threadIdx.x;
    const int tx = tid & 15;
    const int ty = tid >> 4;
    const int bm0 = blockIdx.y << 7;

    float acc[8][8];
#pragma unroll
    for (int i = 0; i < 8; i++)
#pragma unroll
        for (int j = 0; j < 8; j++) acc[i][j] = 0.f;

    for (int k0 = 0; k0 < K; k0 += 16) {
#pragma unroll
        for (int l = 0; l < 2; l++) {
            const int id = tid + (l << 8);
            const int r  = id >> 2;
            const int c4 = id & 3;
            const int grow = bm0 + r;
            float4 av = make_float4(0.f, 0.f, 0.f, 0.f);
            if (grow < M)
                av = *(const float4*)(A + (size_t)grow * K + k0 + (c4 << 2));
            As[(c4 << 2) + 0][r] = av.x;
            As[(c4 << 2) + 1][r] = av.y;
            As[(c4 << 2) + 2][r] = av.z;
            As[(c4 << 2) + 3][r] = av.w;
            const float4 bv4 = *(const float4*)(B + (size_t)r * K + k0 + (c4 << 2));
            Bs[(c4 << 2) + 0][r] = bv4.x;
            Bs[(c4 << 2) + 1][r] = bv4.y;
            Bs[(c4 << 2) + 2][r] = bv4.z;
            Bs[(c4 << 2) + 3][r] = bv4.w;
        }
        __syncthreads();
#pragma unroll
        for (int kk = 0; kk < 16; kk++) {
            float a[8], b[8];
#pragma unroll
            for (int i = 0; i < 8; i++) a[i] = As[kk][(ty << 3) + i];
#pragma unroll
            for (int j = 0; j < 8; j++) b[j] = Bs[kk][(tx << 3) + j];
#pragma unroll
            for (int i = 0; i < 8; i++)
#pragma unroll
                for (int j = 0; j < 8; j++) acc[i][j] += a[i] * b[j];
        }
        __syncthreads();
    }

#pragma unroll
    for (int i = 0; i < 8; i++) {
        const int grow = bm0 + (ty << 3) + i;
        if (grow >= M) break;
        float* crow = C + (size_t)grow * ldc + coff + (tx << 3);
#pragma unroll
        for (int j = 0; j < 8; j += 4) {
            float4 o;
            o.x = acc[i][j]     + bias[(tx << 3) + j];
            o.y = acc[i][j + 1] + bias[(tx << 3) + j + 1];
            o.z = acc[i][j + 2] + bias[(tx << 3) + j + 2];
            o.w = acc[i][j + 3] + bias[(tx << 3) + j + 3];
            *(float4*)(crow + j) = o;
        }
    }
}

// ---------------------------------------------------------------------------
// Output SGEMM with fused softmax normalization:
// out[m,n] = sum_k (acc[m,k] / (s[m, k/16] + 1e-12)) * Wo[n,k] + bo[n]
// K = 128. Since BK=16 and k0 is a multiple of 16, head = k0>>4 is uniform
// across each A-tile load -> one scalar s load per float4.
// ---------------------------------------------------------------------------
__global__ __launch_bounds__(256) void sgemm_out(
    const float* __restrict__ A, const float* __restrict__ B,
    const float* __restrict__ bias, float* __restrict__ C, int M)
{
    __shared__ float As[16][132];
    __shared__ float Bs[16][132];

    const int K = 128, ldc = 128;
    const int tid = threadIdx.x;
    const int tx = tid & 15;
    const int ty = tid >> 4;
    const int bm0 = blockIdx.y << 7;

    float acc[8][8];
#pragma unroll
    for (int i = 0; i < 8; i++)
#pragma unroll
        for (int j = 0; j < 8; j++) acc[i][j] = 0.f;

    for (int k0 = 0; k0 < K; k0 += 16) {
        const int head = k0 >> 4;
#pragma unroll
        for (int l = 0; l < 2; l++) {
            const int id = tid + (l << 8);
            const int r  = id >> 2;
            const int c4 = id & 3;
            const int grow = bm0 + r;
            float4 av = make_float4(0.f, 0.f, 0.f, 0.f);
            if (grow < M) {
                av = *(const float4*)(A + (size_t)grow * K + k0 + (c4 << 2));
                const float rcp = 1.0f / (g_s[(size_t)grow * 8 + head] + 1e-12f);
                av.x *= rcp; av.y *= rcp; av.z *= rcp; av.w *= rcp;
            }
            As[(c4 << 2) + 0][r] = av.x;
            As[(c4 << 2) + 1][r] = av.y;
            As[(c4 << 2) + 2][r] = av.z;
            As[(c4 << 2) + 3][r] = av.w;
            const float4 bv4 = *(const float4*)(B + (size_t)r * K + k0 + (c4 << 2));
            Bs[(c4 << 2) + 0][r] = bv4.x;
            Bs[(c4 << 2) + 1][r] = bv4.y;
            Bs[(c4 << 2) + 2][r] = bv4.z;
            Bs[(c4 << 2) + 3][r] = bv4.w;
        }
        __syncthreads();
#pragma unroll
        for (int kk = 0; kk < 16; kk++) {
            float a[8], b[8];
#pragma unroll
            for (int i = 0; i < 8; i++) a[i] = As[kk][(ty << 3) + i];
#pragma unroll
            for (int j = 0; j < 8; j++) b[j] = Bs[kk][(tx << 3) + j];
#pragma unroll
            for (int i = 0; i < 8; i++)
#pragma unroll
                for (int j = 0; j < 8; j++) acc[i][j] += a[i] * b[j];
        }
        __syncthreads();
    }

#pragma unroll
    for (int i = 0; i < 8; i++) {
        const int grow = bm0 + (ty << 3) + i;
        if (grow >= M) break;
        float* crow = C + (size_t)grow * ldc + (tx << 3);
#pragma unroll
        for (int j = 0; j < 8; j += 4) {
            float4 o;
            o.x = acc[i][j]     + bias[(tx << 3) + j];
            o.y = acc[i][j + 1] + bias[(tx << 3) + j + 1];
            o.z = acc[i][j + 2] + bias[(tx << 3) + j + 2];
            o.w = acc[i][j + 3] + bias[(tx << 3) + j + 3];
            *(float4*)(crow + j) = o;
        }
    }
}

// ---------------------------------------------------------------------------
// Single fused edge pass: geo MLP + logits + exp + denom accumulation +
// UNNORMALIZED weighted scatter of v. One thread per edge, all 8 heads.
// (Softmax division is deferred into sgemm_out: sum(ev/s * v) = (1/s)*sum(ev*v).)
// No segment-max: logits are O(1) here, exp cannot overflow, softmax is
// shift-invariant. centers = linspace(0,6,16) = 0.4*i, gamma = 1.
// ---------------------------------------------------------------------------
__global__ __launch_bounds__(256) void edge_fused(
    const float* __restrict__ dist,
    const float* __restrict__ Wg1, const float* __restrict__ bg1,
    const float* __restrict__ Wg2, const float* __restrict__ bg2,
    int E)
{
    __shared__ float sW1[256], sW2[128], sb1[16], sb2[8];
    const int tid = threadIdx.x;
    sW1[tid] = Wg1[tid];
    if (tid < 128) sW2[tid] = Wg2[tid];
    if (tid < 16)  sb1[tid] = bg1[tid];
    if (tid < 8)   sb2[tid] = bg2[tid];
    __syncthreads();

    const int e = blockIdx.x * 256 + tid;
    if (e >= E) return;

    // --- geo bias for 8 heads ---
    const float d = dist[e];
    float r[16];
#pragma unroll
    for (int i = 0; i < 16; i++) {
        const float t = d - 0.4f * (float)i;
        r[i] = __expf(-t * t);
    }
    float o[8];
#pragma unroll
    for (int h = 0; h < 8; h++) o[h] = sb2[h];
#pragma unroll
    for (int j = 0; j < 16; j++) {
        float hj = sb1[j];
#pragma unroll
        for (int i = 0; i < 16; i++) hj += r[i] * sW1[j * 16 + i];
        hj = fmaxf(hj, 0.f);
#pragma unroll
        for (int h = 0; h < 8; h++) o[h] += hj * sW2[h * 16 + j];
    }

    // --- logits + exp + denom + unnormalized v scatter ---
    const int row = g_idx[e];
    const int col = g_idx[E + e];
    const float4* qp = (const float4*)(g_qkv + (size_t)row * 384);
    const float4* kp = (const float4*)(g_qkv + (size_t)col * 384 + 128);
    const float4* vp = (const float4*)(g_qkv + (size_t)col * 384 + 256);
    float* dst = g_acc + (size_t)row * 128;

#pragma unroll
    for (int h = 0; h < 8; h++) {
        float dot = 0.f;
#pragma unroll
        for (int i = 0; i < 4; i++) {
            const float4 a = qp[h * 4 + i];
            const float4 b = kp[h * 4 + i];
            dot += a.x * b.x + a.y * b.y + a.z * b.z + a.w * b.w;
        }
        const float val = __expf(dot * 0.25f + o[h]);
        atomicAdd(&g_s[(size_t)row * 8 + h], val);
#pragma unroll
        for (int i = 0; i < 4; i++) {
            const float4 v = vp[h * 4 + i];
            asm volatile("red.global.add.v4.f32 [%0], {%1,%2,%3,%4};"
                         :: "l"(dst + h * 16 + i * 4),
                            "f"(val * v.x), "f"(val * v.y), "f"(val * v.z), "f"(val * v.w)
                         : "memory");
        }
    }
}

// ---------------------------------------------------------------------------
extern "C" void kernel_launch(void* const* d_in, const int* in_sizes, int n_in,
                              void* d_out, int out_size)
{
    const float* x    = (const float*)d_in[0];
    const void*  ei   = d_in[1];
    const float* dist = (const float*)d_in[2];
    const float* Wq  = (const float*)d_in[3];  const float* bq  = (const float*)d_in[4];
    const float* Wk  = (const float*)d_in[5];  const float* bk  = (const float*)d_in[6];
    const float* Wv  = (const float*)d_in[7];  const float* bv  = (const float*)d_in[8];
    const float* Wo  = (const float*)d_in[9];  const float* bo  = (const float*)d_in[10];
    const float* Wg1 = (const float*)d_in[11]; const float* bg1 = (const float*)d_in[12];
    const float* Wg2 = (const float*)d_in[13]; const float* bg2 = (const float*)d_in[14];

    const int N = in_sizes[0] / 256;
    const int E = in_sizes[2];
    float* out = (float*)d_out;

    void* p_qkv = nullptr;
    void* p_acc = nullptr;
    cudaGetSymbolAddress(&p_qkv, g_qkv);
    cudaGetSymbolAddress(&p_acc, g_acc);

    detect_idx<<<1, 32>>>(ei, E, N);
    convert_idx<<<(2 * E + 255) / 256, 256>>>(ei, 2 * E);
    zero_bufs<<<(N * 32 + 255) / 256, 256>>>(N);

    const int mblocks = (N + 127) / 128;
    sgemm_qkv<<<dim3(3, mblocks), 256>>>(x, Wq, Wk, Wv, bq, bk, bv, (float*)p_qkv, N);

    edge_fused<<<(E + 255) / 256, 256>>>(dist, Wg1, bg1, Wg2, bg2, E);

    sgemm_out<<<dim3(1, mblocks), 256>>>((const float*)p_acc, Wo, bo, out, N);
}

// round 6
// speedup vs baseline: 1.5245x; 1.5245x over previous
#include <cuda_runtime.h>
#include <cstdint>
#include <cstddef>

// Problem-shape capacities (fixed by the dataset)
#define NODES_CAP 50000
#define EDGES_CAP 800000

// ---------------- device scratch (static: allocation rules) ----------------
__device__ float g_qkv[(size_t)NODES_CAP * 384];   // [N][384] : q|k|v
__device__ float g_geo[(size_t)EDGES_CAP * 8];     // [E][8]   : geo bias
__device__ float g_s  [(size_t)NODES_CAP * 8];     // [N][8]   : softmax denom
__device__ float g_acc[(size_t)NODES_CAP * 128];   // [N][128] : UNNORMALIZED attn out
__device__ int   g_idx[(size_t)EDGES_CAP * 2];     // row | col as int32
__device__ int   g_idx64;                          // 1 if edge_index is int64

// ---------------------------------------------------------------------------
// Index dtype detection + normalization (JAX may emit int32 despite int64 in
// the reference). Convert to flat int32 either way.
// ---------------------------------------------------------------------------
__global__ void detect_idx(const void* __restrict__ ei, int E, int N)
{
    if (blockIdx.x == 0 && threadIdx.x == 0) {
        const long long* p = (const long long*)ei;
        int ok = 1;
        for (int i = 0; i < 64; i++) {
            const long long v = p[i];
            if (v < 0 || v >= (long long)N) { ok = 0; break; }
        }
        g_idx64 = ok;
    }
}

__global__ __launch_bounds__(256) void convert_idx(const void* __restrict__ ei, int total)
{
    const int t = blockIdx.x * 256 + threadIdx.x;
    if (t >= total) return;
    if (g_idx64) g_idx[t] = (int)((const long long*)ei)[t];
    else         g_idx[t] = ((const int*)ei)[t];
}

__global__ __launch_bounds__(256) void zero_bufs(int N)
{
    const int t = blockIdx.x * 256 + threadIdx.x;
    const int n_s   = N * 8 / 4;
    const int n_acc = N * 128 / 4;
    if (t < n_s)   ((float4*)g_s)[t]   = make_float4(0.f, 0.f, 0.f, 0.f);
    if (t < n_acc) ((float4*)g_acc)[t] = make_float4(0.f, 0.f, 0.f, 0.f);
}

// ---------------------------------------------------------------------------
// Merged QKV SGEMM (NT): blockIdx.x in {0,1,2} selects (Wq|Wk|Wv).
// C[m, 128*bx + n] = sum_k x[m,k] * W[n,k] + b[n].  BM=BN=128, BK=16.
// ---------------------------------------------------------------------------
__global__ __launch_bounds__(256) void sgemm_qkv(
    const float* __restrict__ A,
    const float* __restrict__ Wq, const float* __restrict__ Wk, const float* __restrict__ Wv,
    const float* __restrict__ bq, const float* __restrict__ bk, const float* __restrict__ bv,
    float* __restrict__ C, int M)
{
    __shared__ float As[16][132];
    __shared__ float Bs[16][132];

    const float* B    = (blockIdx.x == 0) ? Wq : (blockIdx.x == 1) ? Wk : Wv;
    const float* bias = (blockIdx.x == 0) ? bq : (blockIdx.x == 1) ? bk : bv;
    const int coff = blockIdx.x << 7;
    const int K = 256, ldc = 384;

    const int tid = threadIdx.x;
    const int tx = tid & 15;
    const int ty = tid >> 4;
    const int bm0 = blockIdx.y << 7;

    float acc[8][8];
#pragma unroll
    for (int i = 0; i < 8; i++)
#pragma unroll
        for (int j = 0; j < 8; j++) acc[i][j] = 0.f;

    for (int k0 = 0; k0 < K; k0 += 16) {
#pragma unroll
        for (int l = 0; l < 2; l++) {
            const int id = tid + (l << 8);
            const int r  = id >> 2;
            const int c4 = id & 3;
            const int grow = bm0 + r;
            float4 av = make_float4(0.f, 0.f, 0.f, 0.f);
            if (grow < M)
                av = *(const float4*)(A + (size_t)grow * K + k0 + (c4 << 2));
            As[(c4 << 2) + 0][r] = av.x;
            As[(c4 << 2) + 1][r] = av.y;
            As[(c4 << 2) + 2][r] = av.z;
            As[(c4 << 2) + 3][r] = av.w;
            const float4 bv4 = *(const float4*)(B + (size_t)r * K + k0 + (c4 << 2));
            Bs[(c4 << 2) + 0][r] = bv4.x;
            Bs[(c4 << 2) + 1][r] = bv4.y;
            Bs[(c4 << 2) + 2][r] = bv4.z;
            Bs[(c4 << 2) + 3][r] = bv4.w;
        }
        __syncthreads();
#pragma unroll
        for (int kk = 0; kk < 16; kk++) {
            float a[8], b[8];
#pragma unroll
            for (int i = 0; i < 8; i++) a[i] = As[kk][(ty << 3) + i];
#pragma unroll
            for (int j = 0; j < 8; j++) b[j] = Bs[kk][(tx << 3) + j];
#pragma unroll
            for (int i = 0; i < 8; i++)
#pragma unroll
                for (int j = 0; j < 8; j++) acc[i][j] += a[i] * b[j];
        }
        __syncthreads();
    }

#pragma unroll
    for (int i = 0; i < 8; i++) {
        const int grow = bm0 + (ty << 3) + i;
        if (grow >= M) break;
        float* crow = C + (size_t)grow * ldc + coff + (tx << 3);
#pragma unroll
        for (int j = 0; j < 8; j += 4) {
            float4 o;
            o.x = acc[i][j]     + bias[(tx << 3) + j];
            o.y = acc[i][j + 1] + bias[(tx << 3) + j + 1];
            o.z = acc[i][j + 2] + bias[(tx << 3) + j + 2];
            o.w = acc[i][j + 3] + bias[(tx << 3) + j + 3];
            *(float4*)(crow + j) = o;
        }
    }
}

// ---------------------------------------------------------------------------
// Output SGEMM with fused softmax normalization:
// out[m,n] = sum_k (acc[m,k] / (s[m, k/16] + 1e-12)) * Wo[n,k] + bo[n]
// ---------------------------------------------------------------------------
__global__ __launch_bounds__(256) void sgemm_out(
    const float* __restrict__ A, const float* __restrict__ B,
    const float* __restrict__ bias, float* __restrict__ C, int M)
{
    __shared__ float As[16][132];
    __shared__ float Bs[16][132];

    const int K = 128, ldc = 128;
    const int tid = threadIdx.x;
    const int tx = tid & 15;
    const int ty = tid >> 4;
    const int bm0 = blockIdx.y << 7;

    float acc[8][8];
#pragma unroll
    for (int i = 0; i < 8; i++)
#pragma unroll
        for (int j = 0; j < 8; j++) acc[i][j] = 0.f;

    for (int k0 = 0; k0 < K; k0 += 16) {
        const int head = k0 >> 4;
#pragma unroll
        for (int l = 0; l < 2; l++) {
            const int id = tid + (l << 8);
            const int r  = id >> 2;
            const int c4 = id & 3;
            const int grow = bm0 + r;
            float4 av = make_float4(0.f, 0.f, 0.f, 0.f);
            if (grow < M) {
                av = *(const float4*)(A + (size_t)grow * K + k0 + (c4 << 2));
                const float rcp = 1.0f / (g_s[(size_t)grow * 8 + head] + 1e-12f);
                av.x *= rcp; av.y *= rcp; av.z *= rcp; av.w *= rcp;
            }
            As[(c4 << 2) + 0][r] = av.x;
            As[(c4 << 2) + 1][r] = av.y;
            As[(c4 << 2) + 2][r] = av.z;
            As[(c4 << 2) + 3][r] = av.w;
            const float4 bv4 = *(const float4*)(B + (size_t)r * K + k0 + (c4 << 2));
            Bs[(c4 << 2) + 0][r] = bv4.x;
            Bs[(c4 << 2) + 1][r] = bv4.y;
            Bs[(c4 << 2) + 2][r] = bv4.z;
            Bs[(c4 << 2) + 3][r] = bv4.w;
        }
        __syncthreads();
#pragma unroll
        for (int kk = 0; kk < 16; kk++) {
            float a[8], b[8];
#pragma unroll
            for (int i = 0; i < 8; i++) a[i] = As[kk][(ty << 3) + i];
#pragma unroll
            for (int j = 0; j < 8; j++) b[j] = Bs[kk][(tx << 3) + j];
#pragma unroll
            for (int i = 0; i < 8; i++)
#pragma unroll
                for (int j = 0; j < 8; j++) acc[i][j] += a[i] * b[j];
        }
        __syncthreads();
    }

#pragma unroll
    for (int i = 0; i < 8; i++) {
        const int grow = bm0 + (ty << 3) + i;
        if (grow >= M) break;
        float* crow = C + (size_t)grow * ldc + (tx << 3);
#pragma unroll
        for (int j = 0; j < 8; j += 4) {
            float4 o;
            o.x = acc[i][j]     + bias[(tx << 3) + j];
            o.y = acc[i][j + 1] + bias[(tx << 3) + j + 1];
            o.z = acc[i][j + 2] + bias[(tx << 3) + j + 2];
            o.w = acc[i][j + 3] + bias[(tx << 3) + j + 3];
            *(float4*)(crow + j) = o;
        }
    }
}

// ---------------------------------------------------------------------------
// Geo bias: dense per-edge MLP, one thread per edge -> g_geo[e][8].
// centers = linspace(0,6,16) = 0.4*i, gamma = 1.
// ---------------------------------------------------------------------------
__global__ __launch_bounds__(256) void geo_kernel(
    const float* __restrict__ dist,
    const float* __restrict__ Wg1, const float* __restrict__ bg1,
    const float* __restrict__ Wg2, const float* __restrict__ bg2,
    int E)
{
    __shared__ float sW1[256], sW2[128], sb1[16], sb2[8];
    const int tid = threadIdx.x;
    sW1[tid] = Wg1[tid];
    if (tid < 128) sW2[tid] = Wg2[tid];
    if (tid < 16)  sb1[tid] = bg1[tid];
    if (tid < 8)   sb2[tid] = bg2[tid];
    __syncthreads();

    const int e = blockIdx.x * 256 + tid;
    if (e >= E) return;

    const float d = dist[e];
    float r[16];
#pragma unroll
    for (int i = 0; i < 16; i++) {
        const float t = d - 0.4f * (float)i;
        r[i] = __expf(-t * t);
    }
    float o[8];
#pragma unroll
    for (int h = 0; h < 8; h++) o[h] = sb2[h];
#pragma unroll
    for (int j = 0; j < 16; j++) {
        float hj = sb1[j];
#pragma unroll
        for (int i = 0; i < 16; i++) hj += r[i] * sW1[j * 16 + i];
        hj = fmaxf(hj, 0.f);
#pragma unroll
        for (int h = 0; h < 8; h++) o[h] += hj * sW2[h * 16 + j];
    }
    float* gp = g_geo + (size_t)e * 8;
    *(float4*)(gp + 0) = make_float4(o[0], o[1], o[2], o[3]);
    *(float4*)(gp + 4) = make_float4(o[4], o[5], o[6], o[7]);
}

// ---------------------------------------------------------------------------
// Warp-per-edge attention pass. Lane l owns float4 l of the 128-float node
// row, which is exactly head h = l>>2's slice. So:
//   q/k/v gathers: 512B fully coalesced per warp (4 lines/instr)
//   dot per head : 4-lane shfl_xor reduction
//   scatter      : red.v4 from 32 consecutive 16B chunks (4 lines/instr)
// Unnormalized accumulation (softmax 1/s deferred to sgemm_out). No
// segment-max: logits are O(1) here, exp cannot overflow.
// ---------------------------------------------------------------------------
__global__ __launch_bounds__(256) void edge_warp(int E)
{
    const int e = blockIdx.x * 8 + (threadIdx.x >> 5);
    if (e >= E) return;
    const int l = threadIdx.x & 31;
    const int h = l >> 2;

    const int row = g_idx[e];
    const int col = g_idx[E + e];

    const float4 qv = ((const float4*)(g_qkv + (size_t)row * 384))[l];
    const float4 kv = ((const float4*)(g_qkv + (size_t)col * 384 + 128))[l];
    float part = qv.x * kv.x + qv.y * kv.y + qv.z * kv.z + qv.w * kv.w;
    part += __shfl_xor_sync(0xffffffffu, part, 1);
    part += __shfl_xor_sync(0xffffffffu, part, 2);   // all 4 lanes of head group hold dot_h

    const float geo = g_geo[(size_t)e * 8 + h];
    const float ev = __expf(part * 0.25f + geo);

    if ((l & 3) == 0)
        asm volatile("red.global.add.f32 [%0], %1;"
                     :: "l"(&g_s[(size_t)row * 8 + h]), "f"(ev) : "memory");

    const float4 vv = ((const float4*)(g_qkv + (size_t)col * 384 + 256))[l];
    float* dst = g_acc + (size_t)row * 128 + (l << 2);
    asm volatile("red.global.add.v4.f32 [%0], {%1,%2,%3,%4};"
                 :: "l"(dst),
                    "f"(ev * vv.x), "f"(ev * vv.y), "f"(ev * vv.z), "f"(ev * vv.w)
                 : "memory");
}

// ---------------------------------------------------------------------------
extern "C" void kernel_launch(void* const* d_in, const int* in_sizes, int n_in,
                              void* d_out, int out_size)
{
    const float* x    = (const float*)d_in[0];
    const void*  ei   = d_in[1];
    const float* dist = (const float*)d_in[2];
    const float* Wq  = (const float*)d_in[3];  const float* bq  = (const float*)d_in[4];
    const float* Wk  = (const float*)d_in[5];  const float* bk  = (const float*)d_in[6];
    const float* Wv  = (const float*)d_in[7];  const float* bv  = (const float*)d_in[8];
    const float* Wo  = (const float*)d_in[9];  const float* bo  = (const float*)d_in[10];
    const float* Wg1 = (const float*)d_in[11]; const float* bg1 = (const float*)d_in[12];
    const float* Wg2 = (const float*)d_in[13]; const float* bg2 = (const float*)d_in[14];

    const int N = in_sizes[0] / 256;
    const int E = in_sizes[2];
    float* out = (float*)d_out;

    void* p_qkv = nullptr;
    void* p_acc = nullptr;
    cudaGetSymbolAddress(&p_qkv, g_qkv);
    cudaGetSymbolAddress(&p_acc, g_acc);

    detect_idx<<<1, 32>>>(ei, E, N);
    convert_idx<<<(2 * E + 255) / 256, 256>>>(ei, 2 * E);
    zero_bufs<<<(N * 32 + 255) / 256, 256>>>(N);

    const int mblocks = (N + 127) / 128;
    sgemm_qkv<<<dim3(3, mblocks), 256>>>(x, Wq, Wk, Wv, bq, bk, bv, (float*)p_qkv, N);

    geo_kernel<<<(E + 255) / 256, 256>>>(dist, Wg1, bg1, Wg2, bg2, E);
    edge_warp<<<(E + 7) / 8, 256>>>(E);

    sgemm_out<<<dim3(1, mblocks), 256>>>((const float*)p_acc, Wo, bo, out, N);
}

// round 7
// speedup vs baseline: 1.6118x; 1.0573x over previous
#include <cuda_runtime.h>
#include <mma.h>
#include <cstdint>
#include <cstddef>

using namespace nvcuda;

// Problem-shape capacities (fixed by the dataset)
#define NODES_CAP 50000
#define ROWPAD    128          // tile-overwrite padding for wmma stores
#define EDGES_CAP 800000

// ---------------- device scratch (static: allocation rules) ----------------
__device__ float g_qkv[(size_t)(NODES_CAP + ROWPAD) * 384]; // [N][384] : q|k|v (row-padded)
__device__ float g_geo[(size_t)EDGES_CAP * 8];              // [E][8]   : geo bias
__device__ float g_s  [(size_t)NODES_CAP * 8];              // [N][8]   : softmax denom
__device__ float g_acc[(size_t)NODES_CAP * 128];            // [N][128] : UNNORMALIZED attn out
__device__ float g_opad[(size_t)(NODES_CAP + ROWPAD) * 128];// row-padded final out staging
__device__ int   g_idx[(size_t)EDGES_CAP * 2];              // row | col as int32
__device__ int   g_idx64;                                   // 1 if edge_index is int64

// ---------------------------------------------------------------------------
// Index dtype detection + normalization (JAX may emit int32 despite int64 in
// the reference). Convert to flat int32 either way.
// ---------------------------------------------------------------------------
__global__ void detect_idx(const void* __restrict__ ei, int E, int N)
{
    if (blockIdx.x == 0 && threadIdx.x == 0) {
        const long long* p = (const long long*)ei;
        int ok = 1;
        for (int i = 0; i < 64; i++) {
            const long long v = p[i];
            if (v < 0 || v >= (long long)N) { ok = 0; break; }
        }
        g_idx64 = ok;
    }
}

__global__ __launch_bounds__(256) void convert_idx(const void* __restrict__ ei, int total)
{
    const int t = blockIdx.x * 256 + threadIdx.x;
    if (t >= total) return;
    if (g_idx64) g_idx[t] = (int)((const long long*)ei)[t];
    else         g_idx[t] = ((const int*)ei)[t];
}

__global__ __launch_bounds__(256) void zero_bufs(int N)
{
    const int t = blockIdx.x * 256 + threadIdx.x;
    const int n_s   = N * 8 / 4;
    const int n_acc = N * 128 / 4;
    if (t < n_s)   ((float4*)g_s)[t]   = make_float4(0.f, 0.f, 0.f, 0.f);
    if (t < n_acc) ((float4*)g_acc)[t] = make_float4(0.f, 0.f, 0.f, 0.f);
}

// ---------------------------------------------------------------------------
// TF32 tensor-core GEMM (NT), merged QKV: blockIdx.x in {0,1,2} selects W.
// C[m, 128*bx + n] = sum_k A[m,k]*W[n,k] + b[n].
// BM=BN=128, BK=32; 8 warps as 2(M)x4(N); warp tile 64x32 = 4x2 wmma m16n16k8.
// Bias is folded in by initializing accumulators from a broadcast bias tile.
// C rows are padded (ROWPAD) so full-tile stores past M are safe.
// ---------------------------------------------------------------------------
__global__ __launch_bounds__(256) void gemm_qkv_tf32(
    const float* __restrict__ A,
    const float* __restrict__ Wq, const float* __restrict__ Wk, const float* __restrict__ Wv,
    const float* __restrict__ bq, const float* __restrict__ bk, const float* __restrict__ bv,
    float* __restrict__ C, int M)
{
    __shared__ float As[128 * 36];
    __shared__ float Bs[128 * 36];
    __shared__ float biasS[16 * 136];

    const float* B    = (blockIdx.x == 0) ? Wq : (blockIdx.x == 1) ? Wk : Wv;
    const float* bias = (blockIdx.x == 0) ? bq : (blockIdx.x == 1) ? bk : bv;
    const int coff = blockIdx.x << 7;
    const int K = 256, ldc = 384;

    const int tid = threadIdx.x;
    const int wid = tid >> 5;
    const int warp_m = wid & 1;          // 0..1 (64 rows each)
    const int warp_n = wid >> 1;         // 0..3 (32 cols each)
    const int bm0 = blockIdx.y << 7;

    // broadcast bias tile: 16 identical rows of the 128 bias values
    for (int t = tid; t < 16 * 128; t += 256)
        biasS[(t >> 7) * 136 + (t & 127)] = bias[t & 127];
    __syncthreads();

    wmma::fragment<wmma::accumulator, 16, 16, 8, float> c[4][2];
#pragma unroll
    for (int i = 0; i < 4; i++)
#pragma unroll
        for (int j = 0; j < 2; j++)
            wmma::load_matrix_sync(c[i][j], &biasS[(warp_n << 5) + (j << 4)], 136,
                                   wmma::mem_row_major);

    for (int k0 = 0; k0 < K; k0 += 32) {
        // cooperative tile loads: 128 rows x 32 cols each (4 float4/thread/matrix)
#pragma unroll
        for (int t = tid; t < 1024; t += 256) {
            const int r  = t >> 3;
            const int c4 = (t & 7) << 2;
            const int grow = bm0 + r;
            float4 av = make_float4(0.f, 0.f, 0.f, 0.f);
            if (grow < M) av = *(const float4*)(A + (size_t)grow * K + k0 + c4);
            *(float4*)(As + r * 36 + c4) = av;
            *(float4*)(Bs + r * 36 + c4) = *(const float4*)(B + (size_t)r * K + k0 + c4);
        }
        __syncthreads();

#pragma unroll
        for (int ks = 0; ks < 4; ks++) {
            const int kk = ks << 3;
            wmma::fragment<wmma::matrix_a, 16, 16, 8, wmma::precision::tf32, wmma::row_major> af[4];
            wmma::fragment<wmma::matrix_b, 16, 16, 8, wmma::precision::tf32, wmma::col_major> bf[2];
#pragma unroll
            for (int i = 0; i < 4; i++) {
                wmma::load_matrix_sync(af[i], &As[((warp_m << 6) + (i << 4)) * 36 + kk], 36);
#pragma unroll
                for (int t = 0; t < af[i].num_elements; t++)
                    af[i].x[t] = wmma::__float_to_tf32(af[i].x[t]);
            }
#pragma unroll
            for (int j = 0; j < 2; j++) {
                wmma::load_matrix_sync(bf[j], &Bs[((warp_n << 5) + (j << 4)) * 36 + kk], 36);
#pragma unroll
                for (int t = 0; t < bf[j].num_elements; t++)
                    bf[j].x[t] = wmma::__float_to_tf32(bf[j].x[t]);
            }
#pragma unroll
            for (int i = 0; i < 4; i++)
#pragma unroll
                for (int j = 0; j < 2; j++)
                    wmma::mma_sync(c[i][j], af[i], bf[j], c[i][j]);
        }
        __syncthreads();
    }

#pragma unroll
    for (int i = 0; i < 4; i++) {
        const int m0 = bm0 + (warp_m << 6) + (i << 4);
#pragma unroll
        for (int j = 0; j < 2; j++) {
            const int n0 = coff + (warp_n << 5) + (j << 4);
            wmma::store_matrix_sync(C + (size_t)m0 * ldc + n0, c[i][j], ldc,
                                    wmma::mem_row_major);
        }
    }
}

// ---------------------------------------------------------------------------
// TF32 output GEMM with fused softmax normalization:
// out[m,n] = sum_k (acc[m,k]/(s[m,k>>4]+1e-12)) * Wo[n,k] + bo[n].  K=128.
// Writes to row-padded staging (g_opad); a copy kernel moves it to d_out.
// ---------------------------------------------------------------------------
__global__ __launch_bounds__(256) void gemm_out_tf32(
    const float* __restrict__ A, const float* __restrict__ B,
    const float* __restrict__ bias, float* __restrict__ C, int M)
{
    __shared__ float As[128 * 36];
    __shared__ float Bs[128 * 36];
    __shared__ float biasS[16 * 136];

    const int K = 128, ldc = 128;
    const int tid = threadIdx.x;
    const int wid = tid >> 5;
    const int warp_m = wid & 1;
    const int warp_n = wid >> 1;
    const int bm0 = blockIdx.y << 7;

    for (int t = tid; t < 16 * 128; t += 256)
        biasS[(t >> 7) * 136 + (t & 127)] = bias[t & 127];
    __syncthreads();

    wmma::fragment<wmma::accumulator, 16, 16, 8, float> c[4][2];
#pragma unroll
    for (int i = 0; i < 4; i++)
#pragma unroll
        for (int j = 0; j < 2; j++)
            wmma::load_matrix_sync(c[i][j], &biasS[(warp_n << 5) + (j << 4)], 136,
                                   wmma::mem_row_major);

    for (int k0 = 0; k0 < K; k0 += 32) {
#pragma unroll
        for (int t = tid; t < 1024; t += 256) {
            const int r  = t >> 3;
            const int c4 = (t & 7) << 2;
            const int grow = bm0 + r;
            float4 av = make_float4(0.f, 0.f, 0.f, 0.f);
            if (grow < M) {
                av = *(const float4*)(A + (size_t)grow * K + k0 + c4);
                const int head = (k0 + c4) >> 4;
                const float rcp = 1.0f / (g_s[(size_t)grow * 8 + head] + 1e-12f);
                av.x *= rcp; av.y *= rcp; av.z *= rcp; av.w *= rcp;
            }
            *(float4*)(As + r * 36 + c4) = av;
            *(float4*)(Bs + r * 36 + c4) = *(const float4*)(B + (size_t)r * K + k0 + c4);
        }
        __syncthreads();

#pragma unroll
        for (int ks = 0; ks < 4; ks++) {
            const int kk = ks << 3;
            wmma::fragment<wmma::matrix_a, 16, 16, 8, wmma::precision::tf32, wmma::row_major> af[4];
            wmma::fragment<wmma::matrix_b, 16, 16, 8, wmma::precision::tf32, wmma::col_major> bf[2];
#pragma unroll
            for (int i = 0; i < 4; i++) {
                wmma::load_matrix_sync(af[i], &As[((warp_m << 6) + (i << 4)) * 36 + kk], 36);
#pragma unroll
                for (int t = 0; t < af[i].num_elements; t++)
                    af[i].x[t] = wmma::__float_to_tf32(af[i].x[t]);
            }
#pragma unroll
            for (int j = 0; j < 2; j++) {
                wmma::load_matrix_sync(bf[j], &Bs[((warp_n << 5) + (j << 4)) * 36 + kk], 36);
#pragma unroll
                for (int t = 0; t < bf[j].num_elements; t++)
                    bf[j].x[t] = wmma::__float_to_tf32(bf[j].x[t]);
            }
#pragma unroll
            for (int i = 0; i < 4; i++)
#pragma unroll
                for (int j = 0; j < 2; j++)
                    wmma::mma_sync(c[i][j], af[i], bf[j], c[i][j]);
        }
        __syncthreads();
    }

#pragma unroll
    for (int i = 0; i < 4; i++) {
        const int m0 = bm0 + (warp_m << 6) + (i << 4);
#pragma unroll
        for (int j = 0; j < 2; j++) {
            const int n0 = (warp_n << 5) + (j << 4);
            wmma::store_matrix_sync(C + (size_t)m0 * ldc + n0, c[i][j], ldc,
                                    wmma::mem_row_major);
        }
    }
}

__global__ __launch_bounds__(256) void copy_out(float* __restrict__ dst, int n4)
{
    const int t = blockIdx.x * 256 + threadIdx.x;
    if (t < n4) ((float4*)dst)[t] = ((const float4*)g_opad)[t];
}

// ---------------------------------------------------------------------------
// Geo bias: dense per-edge MLP, one thread per edge -> g_geo[e][8].
// centers = linspace(0,6,16) = 0.4*i, gamma = 1.
// ---------------------------------------------------------------------------
__global__ __launch_bounds__(256) void geo_kernel(
    const float* __restrict__ dist,
    const float* __restrict__ Wg1, const float* __restrict__ bg1,
    const float* __restrict__ Wg2, const float* __restrict__ bg2,
    int E)
{
    __shared__ float sW1[256], sW2[128], sb1[16], sb2[8];
    const int tid = threadIdx.x;
    sW1[tid] = Wg1[tid];
    if (tid < 128) sW2[tid] = Wg2[tid];
    if (tid < 16)  sb1[tid] = bg1[tid];
    if (tid < 8)   sb2[tid] = bg2[tid];
    __syncthreads();

    const int e = blockIdx.x * 256 + tid;
    if (e >= E) return;

    const float d = dist[e];
    float r[16];
#pragma unroll
    for (int i = 0; i < 16; i++) {
        const float t = d - 0.4f * (float)i;
        r[i] = __expf(-t * t);
    }
    float o[8];
#pragma unroll
    for (int h = 0; h < 8; h++) o[h] = sb2[h];
#pragma unroll
    for (int j = 0; j < 16; j++) {
        float hj = sb1[j];
#pragma unroll
        for (int i = 0; i < 16; i++) hj += r[i] * sW1[j * 16 + i];
        hj = fmaxf(hj, 0.f);
#pragma unroll
        for (int h = 0; h < 8; h++) o[h] += hj * sW2[h * 16 + j];
    }
    float* gp = g_geo + (size_t)e * 8;
    *(float4*)(gp + 0) = make_float4(o[0], o[1], o[2], o[3]);
    *(float4*)(gp + 4) = make_float4(o[4], o[5], o[6], o[7]);
}

// ---------------------------------------------------------------------------
// Warp-per-edge attention pass (coalesced gathers + red.v4 scatter).
// Unnormalized accumulation; softmax 1/s deferred into gemm_out_tf32.
// ---------------------------------------------------------------------------
__global__ __launch_bounds__(256) void edge_warp(int E)
{
    const int e = blockIdx.x * 8 + (threadIdx.x >> 5);
    if (e >= E) return;
    const int l = threadIdx.x & 31;
    const int h = l >> 2;

    const int row = g_idx[e];
    const int col = g_idx[E + e];

    const float4 qv = ((const float4*)(g_qkv + (size_t)row * 384))[l];
    const float4 kv = ((const float4*)(g_qkv + (size_t)col * 384 + 128))[l];
    float part = qv.x * kv.x + qv.y * kv.y + qv.z * kv.z + qv.w * kv.w;
    part += __shfl_xor_sync(0xffffffffu, part, 1);
    part += __shfl_xor_sync(0xffffffffu, part, 2);

    const float geo = g_geo[(size_t)e * 8 + h];
    const float ev = __expf(part * 0.25f + geo);

    if ((l & 3) == 0)
        asm volatile("red.global.add.f32 [%0], %1;"
                     :: "l"(&g_s[(size_t)row * 8 + h]), "f"(ev) : "memory");

    const float4 vv = ((const float4*)(g_qkv + (size_t)col * 384 + 256))[l];
    float* dst = g_acc + (size_t)row * 128 + (l << 2);
    asm volatile("red.global.add.v4.f32 [%0], {%1,%2,%3,%4};"
                 :: "l"(dst),
                    "f"(ev * vv.x), "f"(ev * vv.y), "f"(ev * vv.z), "f"(ev * vv.w)
                 : "memory");
}

// ---------------------------------------------------------------------------
extern "C" void kernel_launch(void* const* d_in, const int* in_sizes, int n_in,
                              void* d_out, int out_size)
{
    const float* x    = (const float*)d_in[0];
    const void*  ei   = d_in[1];
    const float* dist = (const float*)d_in[2];
    const float* Wq  = (const float*)d_in[3];  const float* bq  = (const float*)d_in[4];
    const float* Wk  = (const float*)d_in[5];  const float* bk  = (const float*)d_in[6];
    const float* Wv  = (const float*)d_in[7];  const float* bv  = (const float*)d_in[8];
    const float* Wo  = (const float*)d_in[9];  const float* bo  = (const float*)d_in[10];
    const float* Wg1 = (const float*)d_in[11]; const float* bg1 = (const float*)d_in[12];
    const float* Wg2 = (const float*)d_in[13]; const float* bg2 = (const float*)d_in[14];

    const int N = in_sizes[0] / 256;
    const int E = in_sizes[2];
    float* out = (float*)d_out;

    void* p_qkv = nullptr;
    void* p_acc = nullptr;
    void* p_opad = nullptr;
    cudaGetSymbolAddress(&p_qkv, g_qkv);
    cudaGetSymbolAddress(&p_acc, g_acc);
    cudaGetSymbolAddress(&p_opad, g_opad);

    detect_idx<<<1, 32>>>(ei, E, N);
    convert_idx<<<(2 * E + 255) / 256, 256>>>(ei, 2 * E);
    zero_bufs<<<(N * 32 + 255) / 256, 256>>>(N);

    const int mblocks = (N + 127) / 128;
    gemm_qkv_tf32<<<dim3(3, mblocks), 256>>>(x, Wq, Wk, Wv, bq, bk, bv, (float*)p_qkv, N);

    geo_kernel<<<(E + 255) / 256, 256>>>(dist, Wg1, bg1, Wg2, bg2, E);
    edge_warp<<<(E + 7) / 8, 256>>>(E);

    gemm_out_tf32<<<dim3(1, mblocks), 256>>>((const float*)p_acc, Wo, bo, (float*)p_opad, N);
    copy_out<<<(N * 32 + 255) / 256, 256>>>(out, N * 32);
}

// round 8
// speedup vs baseline: 1.7415x; 1.0805x over previous
#include <cuda_runtime.h>
#include <mma.h>
#include <cstdint>
#include <cstddef>

using namespace nvcuda;

// Problem-shape capacities (fixed by the dataset)
#define NODES_CAP 50000
#define ROWPAD    128          // tile-overwrite padding for wmma stores
#define EDGES_CAP 800000

// ---------------- device scratch (static: allocation rules) ----------------
__device__ float g_qkv[(size_t)(NODES_CAP + ROWPAD) * 384]; // [N][384] : q|k|v (row-padded)
__device__ float g_geo[(size_t)EDGES_CAP * 8];              // [E][8]   : geo bias
__device__ float g_s  [(size_t)NODES_CAP * 8];              // [N][8]   : softmax denom
__device__ float g_acc[(size_t)NODES_CAP * 128];            // [N][128] : UNNORMALIZED attn out
__device__ float g_opad[(size_t)(NODES_CAP + ROWPAD) * 128];// row-padded final out staging
__device__ int   g_idx[(size_t)EDGES_CAP * 2];              // row | col as int32
__device__ int   g_idx64;                                   // 1 if edge_index is int64

// ---------------------------------------------------------------------------
__global__ void detect_idx(const void* __restrict__ ei, int E, int N)
{
    if (blockIdx.x == 0 && threadIdx.x == 0) {
        const long long* p = (const long long*)ei;
        int ok = 1;
        for (int i = 0; i < 64; i++) {
            const long long v = p[i];
            if (v < 0 || v >= (long long)N) { ok = 0; break; }
        }
        g_idx64 = ok;
    }
}

__global__ __launch_bounds__(256) void convert_idx(const void* __restrict__ ei, int total)
{
    const int t = blockIdx.x * 256 + threadIdx.x;
    if (t >= total) return;
    if (g_idx64) g_idx[t] = (int)((const long long*)ei)[t];
    else         g_idx[t] = ((const int*)ei)[t];
}

__global__ __launch_bounds__(256) void zero_bufs(int N)
{
    const int t = blockIdx.x * 256 + threadIdx.x;
    const int n_s   = N * 8 / 4;
    const int n_acc = N * 128 / 4;
    if (t < n_s)   ((float4*)g_s)[t]   = make_float4(0.f, 0.f, 0.f, 0.f);
    if (t < n_acc) ((float4*)g_acc)[t] = make_float4(0.f, 0.f, 0.f, 0.f);
}

// ---------------------------------------------------------------------------
// Register-prefetch pipelined TF32 GEMM core (NT layout).
// C[m, coff+n] = sum_k A[m,k]*B[n,k] + bias[n], optional per-element A scaling
// by 1/(s[m][k>>4]+1e-12) when SCALE (softmax normalization fusion).
// BM=BN=128, BK=32; 8 warps 2(M)x4(N), warp tile 64x32 = 4x2 wmma m16n16k8.
// While tensor cores compute tile kt, tile kt+1 is in flight into registers;
// after compute+sync it is stored to the (single) smem buffer.
// C must be row-padded so full-tile stores past M are safe.
// ---------------------------------------------------------------------------
template<int K, bool SCALE>
__device__ __forceinline__ void gemm_core(
    const float* __restrict__ A, const float* __restrict__ B,
    const float* __restrict__ bias, float* __restrict__ C,
    int M, int ldc, int coff, int bm0)
{
    __shared__ float As[128 * 36];
    __shared__ float Bs[128 * 36];
    __shared__ float biasS[16 * 136];

    const int tid = threadIdx.x;
    const int wid = tid >> 5;
    const int warp_m = wid & 1;          // 0..1 (64 rows each)
    const int warp_n = wid >> 1;         // 0..3 (32 cols each)

    for (int t = tid; t < 16 * 128; t += 256)
        biasS[(t >> 7) * 136 + (t & 127)] = bias[t & 127];
    __syncthreads();

    wmma::fragment<wmma::accumulator, 16, 16, 8, float> c[4][2];
#pragma unroll
    for (int i = 0; i < 4; i++)
#pragma unroll
        for (int j = 0; j < 2; j++)
            wmma::load_matrix_sync(c[i][j], &biasS[(warp_n << 5) + (j << 4)], 136,
                                   wmma::mem_row_major);

    float4 ar[4], br[4];

    // ---- prologue: fetch tile 0 into regs, store to smem ----
#pragma unroll
    for (int l = 0; l < 4; l++) {
        const int idx = tid + (l << 8);
        const int r  = idx >> 3;
        const int c4 = (idx & 7) << 2;
        const int grow = bm0 + r;
        float4 av = make_float4(0.f, 0.f, 0.f, 0.f);
        if (grow < M) {
            av = *(const float4*)(A + (size_t)grow * K + c4);
            if (SCALE) {
                const float rcp = 1.0f / (g_s[(size_t)grow * 8 + (c4 >> 4)] + 1e-12f);
                av.x *= rcp; av.y *= rcp; av.z *= rcp; av.w *= rcp;
            }
        }
        ar[l] = av;
        br[l] = *(const float4*)(B + (size_t)r * K + c4);
    }
#pragma unroll
    for (int l = 0; l < 4; l++) {
        const int idx = tid + (l << 8);
        const int r  = idx >> 3;
        const int c4 = (idx & 7) << 2;
        *(float4*)(As + r * 36 + c4) = ar[l];
        *(float4*)(Bs + r * 36 + c4) = br[l];
    }
    __syncthreads();

    constexpr int NT = K / 32;
#pragma unroll
    for (int kt = 0; kt < NT; kt++) {
        // ---- issue prefetch of next tile (overlaps with mma below) ----
        if (kt + 1 < NT) {
            const int k0 = (kt + 1) << 5;
#pragma unroll
            for (int l = 0; l < 4; l++) {
                const int idx = tid + (l << 8);
                const int r  = idx >> 3;
                const int c4 = (idx & 7) << 2;
                const int grow = bm0 + r;
                float4 av = make_float4(0.f, 0.f, 0.f, 0.f);
                if (grow < M) {
                    av = *(const float4*)(A + (size_t)grow * K + k0 + c4);
                    if (SCALE) {
                        const float rcp =
                            1.0f / (g_s[(size_t)grow * 8 + ((k0 + c4) >> 4)] + 1e-12f);
                        av.x *= rcp; av.y *= rcp; av.z *= rcp; av.w *= rcp;
                    }
                }
                ar[l] = av;
                br[l] = *(const float4*)(B + (size_t)r * K + k0 + c4);
            }
        }

        // ---- compute on current smem tile ----
#pragma unroll
        for (int ks = 0; ks < 4; ks++) {
            const int kk = ks << 3;
            wmma::fragment<wmma::matrix_a, 16, 16, 8, wmma::precision::tf32, wmma::row_major> af[4];
            wmma::fragment<wmma::matrix_b, 16, 16, 8, wmma::precision::tf32, wmma::col_major> bf[2];
#pragma unroll
            for (int i = 0; i < 4; i++) {
                wmma::load_matrix_sync(af[i], &As[((warp_m << 6) + (i << 4)) * 36 + kk], 36);
#pragma unroll
                for (int t = 0; t < af[i].num_elements; t++)
                    af[i].x[t] = wmma::__float_to_tf32(af[i].x[t]);
            }
#pragma unroll
            for (int j = 0; j < 2; j++) {
                wmma::load_matrix_sync(bf[j], &Bs[((warp_n << 5) + (j << 4)) * 36 + kk], 36);
#pragma unroll
                for (int t = 0; t < bf[j].num_elements; t++)
                    bf[j].x[t] = wmma::__float_to_tf32(bf[j].x[t]);
            }
#pragma unroll
            for (int i = 0; i < 4; i++)
#pragma unroll
                for (int j = 0; j < 2; j++)
                    wmma::mma_sync(c[i][j], af[i], bf[j], c[i][j]);
        }
        __syncthreads();

        // ---- commit prefetched tile to smem ----
        if (kt + 1 < NT) {
#pragma unroll
            for (int l = 0; l < 4; l++) {
                const int idx = tid + (l << 8);
                const int r  = idx >> 3;
                const int c4 = (idx & 7) << 2;
                *(float4*)(As + r * 36 + c4) = ar[l];
                *(float4*)(Bs + r * 36 + c4) = br[l];
            }
            __syncthreads();
        }
    }

#pragma unroll
    for (int i = 0; i < 4; i++) {
        const int m0 = bm0 + (warp_m << 6) + (i << 4);
#pragma unroll
        for (int j = 0; j < 2; j++) {
            const int n0 = coff + (warp_n << 5) + (j << 4);
            wmma::store_matrix_sync(C + (size_t)m0 * ldc + n0, c[i][j], ldc,
                                    wmma::mem_row_major);
        }
    }
}

// Merged QKV: blockIdx.x in {0,1,2} selects (Wq|Wk|Wv).
__global__ __launch_bounds__(256) void gemm_qkv_tf32(
    const float* __restrict__ A,
    const float* __restrict__ Wq, const float* __restrict__ Wk, const float* __restrict__ Wv,
    const float* __restrict__ bq, const float* __restrict__ bk, const float* __restrict__ bv,
    float* __restrict__ C, int M)
{
    const float* B    = (blockIdx.x == 0) ? Wq : (blockIdx.x == 1) ? Wk : Wv;
    const float* bias = (blockIdx.x == 0) ? bq : (blockIdx.x == 1) ? bk : bv;
    gemm_core<256, false>(A, B, bias, C, M, 384, blockIdx.x << 7, blockIdx.y << 7);
}

// Output GEMM with fused softmax normalization (1/s on A loads).
__global__ __launch_bounds__(256) void gemm_out_tf32(
    const float* __restrict__ A, const float* __restrict__ B,
    const float* __restrict__ bias, float* __restrict__ C, int M)
{
    gemm_core<128, true>(A, B, bias, C, M, 128, 0, blockIdx.y << 7);
}

__global__ __launch_bounds__(256) void copy_out(float* __restrict__ dst, int n4)
{
    const int t = blockIdx.x * 256 + threadIdx.x;
    if (t < n4) ((float4*)dst)[t] = ((const float4*)g_opad)[t];
}

// ---------------------------------------------------------------------------
// Geo bias: dense per-edge MLP, one thread per edge -> g_geo[e][8].
// centers = linspace(0,6,16) = 0.4*i, gamma = 1.
// ---------------------------------------------------------------------------
__global__ __launch_bounds__(256) void geo_kernel(
    const float* __restrict__ dist,
    const float* __restrict__ Wg1, const float* __restrict__ bg1,
    const float* __restrict__ Wg2, const float* __restrict__ bg2,
    int E)
{
    __shared__ float sW1[256], sW2[128], sb1[16], sb2[8];
    const int tid = threadIdx.x;
    sW1[tid] = Wg1[tid];
    if (tid < 128) sW2[tid] = Wg2[tid];
    if (tid < 16)  sb1[tid] = bg1[tid];
    if (tid < 8)   sb2[tid] = bg2[tid];
    __syncthreads();

    const int e = blockIdx.x * 256 + tid;
    if (e >= E) return;

    const float d = dist[e];
    float r[16];
#pragma unroll
    for (int i = 0; i < 16; i++) {
        const float t = d - 0.4f * (float)i;
        r[i] = __expf(-t * t);
    }
    float o[8];
#pragma unroll
    for (int h = 0; h < 8; h++) o[h] = sb2[h];
#pragma unroll
    for (int j = 0; j < 16; j++) {
        float hj = sb1[j];
#pragma unroll
        for (int i = 0; i < 16; i++) hj += r[i] * sW1[j * 16 + i];
        hj = fmaxf(hj, 0.f);
#pragma unroll
        for (int h = 0; h < 8; h++) o[h] += hj * sW2[h * 16 + j];
    }
    float* gp = g_geo + (size_t)e * 8;
    *(float4*)(gp + 0) = make_float4(o[0], o[1], o[2], o[3]);
    *(float4*)(gp + 4) = make_float4(o[4], o[5], o[6], o[7]);
}

// ---------------------------------------------------------------------------
// Warp-per-edge attention pass (coalesced gathers + red.v4 scatter).
// Unnormalized accumulation; softmax 1/s deferred into gemm_out_tf32.
// No segment-max: logits are O(1) here, exp cannot overflow.
// ---------------------------------------------------------------------------
__global__ __launch_bounds__(256) void edge_warp(int E)
{
    const int e = blockIdx.x * 8 + (threadIdx.x >> 5);
    if (e >= E) return;
    const int l = threadIdx.x & 31;
    const int h = l >> 2;

    const int row = g_idx[e];
    const int col = g_idx[E + e];

    const float4 qv = ((const float4*)(g_qkv + (size_t)row * 384))[l];
    const float4 kv = ((const float4*)(g_qkv + (size_t)col * 384 + 128))[l];
    float part = qv.x * kv.x + qv.y * kv.y + qv.z * kv.z + qv.w * kv.w;
    part += __shfl_xor_sync(0xffffffffu, part, 1);
    part += __shfl_xor_sync(0xffffffffu, part, 2);

    const float geo = g_geo[(size_t)e * 8 + h];
    const float ev = __expf(part * 0.25f + geo);

    if ((l & 3) == 0)
        asm volatile("red.global.add.f32 [%0], %1;"
                     :: "l"(&g_s[(size_t)row * 8 + h]), "f"(ev) : "memory");

    const float4 vv = ((const float4*)(g_qkv + (size_t)col * 384 + 256))[l];
    float* dst = g_acc + (size_t)row * 128 + (l << 2);
    asm volatile("red.global.add.v4.f32 [%0], {%1,%2,%3,%4};"
                 :: "l"(dst),
                    "f"(ev * vv.x), "f"(ev * vv.y), "f"(ev * vv.z), "f"(ev * vv.w)
                 : "memory");
}

// ---------------------------------------------------------------------------
extern "C" void kernel_launch(void* const* d_in, const int* in_sizes, int n_in,
                              void* d_out, int out_size)
{
    const float* x    = (const float*)d_in[0];
    const void*  ei   = d_in[1];
    const float* dist = (const float*)d_in[2];
    const float* Wq  = (const float*)d_in[3];  const float* bq  = (const float*)d_in[4];
    const float* Wk  = (const float*)d_in[5];  const float* bk  = (const float*)d_in[6];
    const float* Wv  = (const float*)d_in[7];  const float* bv  = (const float*)d_in[8];
    const float* Wo  = (const float*)d_in[9];  const float* bo  = (const float*)d_in[10];
    const float* Wg1 = (const float*)d_in[11]; const float* bg1 = (const float*)d_in[12];
    const float* Wg2 = (const float*)d_in[13]; const float* bg2 = (const float*)d_in[14];

    const int N = in_sizes[0] / 256;
    const int E = in_sizes[2];
    float* out = (float*)d_out;

    void* p_qkv = nullptr;
    void* p_acc = nullptr;
    void* p_opad = nullptr;
    cudaGetSymbolAddress(&p_qkv, g_qkv);
    cudaGetSymbolAddress(&p_acc, g_acc);
    cudaGetSymbolAddress(&p_opad, g_opad);

    detect_idx<<<1, 32>>>(ei, E, N);
    convert_idx<<<(2 * E + 255) / 256, 256>>>(ei, 2 * E);
    zero_bufs<<<(N * 32 + 255) / 256, 256>>>(N);

    const int mblocks = (N + 127) / 128;
    gemm_qkv_tf32<<<dim3(3, mblocks), 256>>>(x, Wq, Wk, Wv, bq, bk, bv, (float*)p_qkv, N);

    geo_kernel<<<(E + 255) / 256, 256>>>(dist, Wg1, bg1, Wg2, bg2, E);
    edge_warp<<<(E + 7) / 8, 256>>>(E);

    gemm_out_tf32<<<dim3(1, mblocks), 256>>>((const float*)p_acc, Wo, bo, (float*)p_opad, N);
    copy_out<<<(N * 32 + 255) / 256, 256>>>(out, N * 32);
}

// round 12
// speedup vs baseline: 1.7668x; 1.0145x over previous
#include <cuda_runtime.h>
#include <mma.h>
#include <cstdint>
#include <cstddef>

using namespace nvcuda;

// Problem-shape capacities (fixed by the dataset)
#define NODES_CAP 50000
#define ROWPAD    128          // tile-overwrite padding
#define EDGES_CAP 800000

// ---------------- device scratch (static: allocation rules) ----------------
__device__ float g_qkv[(size_t)(NODES_CAP + ROWPAD) * 384]; // [N][384] q|k|v fp32 (row-padded)
__device__ float g_geo[(size_t)EDGES_CAP * 8];              // [E][8] geo bias
__device__ float g_s  [(size_t)(NODES_CAP + ROWPAD) * 8];   // [N][8] softmax denom (padded)
__device__ float g_acc[(size_t)NODES_CAP * 128];            // [N][128] UNNORMALIZED attn out
__device__ float g_opad[(size_t)(NODES_CAP + ROWPAD) * 128];// row-padded final out staging
__device__ int   g_idx[(size_t)EDGES_CAP * 2];              // row | col as int32
__device__ int   g_idx64;

// ---------------------------------------------------------------------------
__global__ void detect_idx(const void* __restrict__ ei, int E, int N)
{
    if (blockIdx.x == 0 && threadIdx.x == 0) {
        const long long* p = (const long long*)ei;
        int ok = 1;
        for (int i = 0; i < 64; i++) {
            const long long v = p[i];
            if (v < 0 || v >= (long long)N) { ok = 0; break; }
        }
        g_idx64 = ok;
    }
}

__global__ __launch_bounds__(256) void convert_idx(const void* __restrict__ ei, int total)
{
    const int t = blockIdx.x * 256 + threadIdx.x;
    if (t >= total) return;
    if (g_idx64) g_idx[t] = (int)((const long long*)ei)[t];
    else         g_idx[t] = ((const int*)ei)[t];
}

__global__ __launch_bounds__(256) void zero_bufs(int N)
{
    const int t = blockIdx.x * 256 + threadIdx.x;
    const int n_s   = (N + ROWPAD) * 8 / 4;
    const int n_acc = N * 128 / 4;
    if (t < n_s)   ((float4*)g_s)[t]   = make_float4(0.f, 0.f, 0.f, 0.f);
    if (t < n_acc) ((float4*)g_acc)[t] = make_float4(0.f, 0.f, 0.f, 0.f);
}

// ---------------------------------------------------------------------------
// cp.async double-buffered TF32 GEMM core (NT layout).
// C[m, coff+n] = sum_k A[m,k]*B[n,k] + bias[n].
// BM=BN=128, BK=32; 8 warps 2(M)x4(N); warp tile 64x32 = 4x2 wmma m16n16k8.
// SCALE: multiply A rows in smem by 1/(g_s[m][head]+1e-12) (softmax fusion);
// BK=32 covers exactly 2 heads -> thread=(row, 16-col half).
// C is row-padded so full-tile stores past M are safe.
// Dynamic smem: 2 stages x (As 128x36 + Bs 128x36) + bias 16x136.
// ---------------------------------------------------------------------------
#define STAGE_F (128 * 36 * 2)
#define GEMM_SMEM_BYTES ((2 * STAGE_F + 16 * 136) * 4)

template<int K, bool SCALE>
__device__ __forceinline__ void gemm_core(
    const float* __restrict__ A, const float* __restrict__ B,
    const float* __restrict__ bias, float* __restrict__ C,
    int M, int ldc, int coff, int bm0)
{
    extern __shared__ float smem[];
    float* biasS = smem + 2 * STAGE_F;

    const int tid = threadIdx.x;
    const int wid = tid >> 5;
    const int warp_m = wid & 1;
    const int warp_n = wid >> 1;

    for (int t = tid; t < 16 * 128; t += 256)
        biasS[(t >> 7) * 136 + (t & 127)] = bias[t & 127];
    __syncthreads();

    wmma::fragment<wmma::accumulator, 16, 16, 8, float> c[4][2];
#pragma unroll
    for (int i = 0; i < 4; i++)
#pragma unroll
        for (int j = 0; j < 2; j++)
            wmma::load_matrix_sync(c[i][j], &biasS[(warp_n << 5) + (j << 4)], 136,
                                   wmma::mem_row_major);

    constexpr int NT = K / 32;

    auto issue_stage = [&](int kt) {
        float* As = smem + (kt & 1) * STAGE_F;
        float* Bs = As + 128 * 36;
        const int k0 = kt << 5;
#pragma unroll
        for (int l = 0; l < 4; l++) {
            const int idx = tid + (l << 8);
            const int r  = idx >> 3;
            const int c4 = (idx & 7) << 2;
            const int grow = bm0 + r;
            const int ok = grow < M;
            const float* ga = A + (size_t)(ok ? grow : 0) * K + k0 + c4;
            const uint32_t sa = (uint32_t)__cvta_generic_to_shared(As + r * 36 + c4);
            const int sz = ok ? 16 : 0;   // src-size 0 -> zero-fill 16B
            asm volatile("cp.async.cg.shared.global [%0], [%1], 16, %2;"
                         :: "r"(sa), "l"(ga), "r"(sz));
            const float* gb = B + (size_t)r * K + k0 + c4;
            const uint32_t sb = (uint32_t)__cvta_generic_to_shared(Bs + r * 36 + c4);
            asm volatile("cp.async.cg.shared.global [%0], [%1], 16;"
                         :: "r"(sb), "l"(gb));
        }
        asm volatile("cp.async.commit_group;");
    };

    issue_stage(0);

    for (int kt = 0; kt < NT; kt++) {
        asm volatile("cp.async.wait_group 0;");
        __syncthreads();

        if (kt + 1 < NT) issue_stage(kt + 1);

        float* As = smem + (kt & 1) * STAGE_F;
        float* Bs = As + 128 * 36;

        if (SCALE) {
            const int r = tid >> 1;
            const int half = tid & 1;
            const int grow = bm0 + r;
            const float rcp = 1.0f / (g_s[(size_t)grow * 8 + (kt << 1) + half] + 1e-12f);
            float* p = As + r * 36 + (half << 4);
#pragma unroll
            for (int i = 0; i < 16; i++) p[i] *= rcp;
            __syncthreads();
        }

#pragma unroll
        for (int ks = 0; ks < 4; ks++) {
            const int kk = ks << 3;
            wmma::fragment<wmma::matrix_a, 16, 16, 8, wmma::precision::tf32, wmma::row_major> af[4];
            wmma::fragment<wmma::matrix_b, 16, 16, 8, wmma::precision::tf32, wmma::col_major> bf[2];
#pragma unroll
            for (int i = 0; i < 4; i++) {
                wmma::load_matrix_sync(af[i], &As[((warp_m << 6) + (i << 4)) * 36 + kk], 36);
#pragma unroll
                for (int t = 0; t < af[i].num_elements; t++)
                    af[i].x[t] = wmma::__float_to_tf32(af[i].x[t]);
            }
#pragma unroll
            for (int j = 0; j < 2; j++) {
                wmma::load_matrix_sync(bf[j], &Bs[((warp_n << 5) + (j << 4)) * 36 + kk], 36);
#pragma unroll
                for (int t = 0; t < bf[j].num_elements; t++)
                    bf[j].x[t] = wmma::__float_to_tf32(bf[j].x[t]);
            }
#pragma unroll
            for (int i = 0; i < 4; i++)
#pragma unroll
                for (int j = 0; j < 2; j++)
                    wmma::mma_sync(c[i][j], af[i], bf[j], c[i][j]);
        }
    }

#pragma unroll
    for (int i = 0; i < 4; i++) {
        const int m0 = bm0 + (warp_m << 6) + (i << 4);
#pragma unroll
        for (int j = 0; j < 2; j++) {
            const int n0 = coff + (warp_n << 5) + (j << 4);
            wmma::store_matrix_sync(C + (size_t)m0 * ldc + n0, c[i][j], ldc,
                                    wmma::mem_row_major);
        }
    }
}

// Merged QKV: blockIdx.x in {0,1,2} selects (Wq|Wk|Wv). fp32 qkv out.
__global__ __launch_bounds__(256) void gemm_qkv_tf32(
    const float* __restrict__ A,
    const float* __restrict__ Wq, const float* __restrict__ Wk, const float* __restrict__ Wv,
    const float* __restrict__ bq, const float* __restrict__ bk, const float* __restrict__ bv,
    int M)
{
    const float* B    = (blockIdx.x == 0) ? Wq : (blockIdx.x == 1) ? Wk : Wv;
    const float* bias = (blockIdx.x == 0) ? bq : (blockIdx.x == 1) ? bk : bv;
    gemm_core<256, false>(A, B, bias, g_qkv, M, 384, blockIdx.x << 7, blockIdx.y << 7);
}

// Output GEMM: fused softmax normalization, fp32 to padded staging.
__global__ __launch_bounds__(256) void gemm_out_tf32(
    const float* __restrict__ A, const float* __restrict__ B,
    const float* __restrict__ bias, int M)
{
    gemm_core<128, true>(A, B, bias, g_opad, M, 128, 0, blockIdx.y << 7);
}

__global__ __launch_bounds__(256) void copy_out(float* __restrict__ dst, int n4)
{
    const int t = blockIdx.x * 256 + threadIdx.x;
    if (t < n4) ((float4*)dst)[t] = ((const float4*)g_opad)[t];
}

// ---------------------------------------------------------------------------
// Geo bias: dense per-edge MLP, one thread per edge -> g_geo[e][8].
// centers = linspace(0,6,16) = 0.4*i, gamma = 1.
// ---------------------------------------------------------------------------
__global__ __launch_bounds__(256) void geo_kernel(
    const float* __restrict__ dist,
    const float* __restrict__ Wg1, const float* __restrict__ bg1,
    const float* __restrict__ Wg2, const float* __restrict__ bg2,
    int E)
{
    __shared__ float sW1[256], sW2[128], sb1[16], sb2[8];
    const int tid = threadIdx.x;
    sW1[tid] = Wg1[tid];
    if (tid < 128) sW2[tid] = Wg2[tid];
    if (tid < 16)  sb1[tid] = bg1[tid];
    if (tid < 8)   sb2[tid] = bg2[tid];
    __syncthreads();

    const int e = blockIdx.x * 256 + tid;
    if (e >= E) return;

    const float d = dist[e];
    float r[16];
#pragma unroll
    for (int i = 0; i < 16; i++) {
        const float t = d - 0.4f * (float)i;
        r[i] = __expf(-t * t);
    }
    float o[8];
#pragma unroll
    for (int h = 0; h < 8; h++) o[h] = sb2[h];
#pragma unroll
    for (int j = 0; j < 16; j++) {
        float hj = sb1[j];
#pragma unroll
        for (int i = 0; i < 16; i++) hj += r[i] * sW1[j * 16 + i];
        hj = fmaxf(hj, 0.f);
#pragma unroll
        for (int h = 0; h < 8; h++) o[h] += hj * sW2[h * 16 + j];
    }
    float* gp = g_geo + (size_t)e * 8;
    *(float4*)(gp + 0) = make_float4(o[0], o[1], o[2], o[3]);
    *(float4*)(gp + 4) = make_float4(o[4], o[5], o[6], o[7]);
}

// ---------------------------------------------------------------------------
// Warp-per-edge attention pass (fp32, coalesced gathers + red.v4 scatter).
// Lane l owns float4 l of the 128-float node row (head h=l>>2).
// Unnormalized accumulation; softmax 1/s deferred into gemm_out_tf32.
// No segment-max: logits are O(1) here, exp cannot overflow.
// ---------------------------------------------------------------------------
__global__ __launch_bounds__(256) void edge_warp(int E)
{
    const int e = blockIdx.x * 8 + (threadIdx.x >> 5);
    if (e >= E) return;
    const int l = threadIdx.x & 31;
    const int h = l >> 2;

    const int row = g_idx[e];
    const int col = g_idx[E + e];

    const float4 qv = ((const float4*)(g_qkv + (size_t)row * 384))[l];
    const float4 kv = ((const float4*)(g_qkv + (size_t)col * 384 + 128))[l];
    float part = qv.x * kv.x + qv.y * kv.y + qv.z * kv.z + qv.w * kv.w;
    part += __shfl_xor_sync(0xffffffffu, part, 1);
    part += __shfl_xor_sync(0xffffffffu, part, 2);

    const float geo = g_geo[(size_t)e * 8 + h];
    const float ev = __expf(part * 0.25f + geo);

    if ((l & 3) == 0)
        asm volatile("red.global.add.f32 [%0], %1;"
                     :: "l"(&g_s[(size_t)row * 8 + h]), "f"(ev) : "memory");

    const float4 vv = ((const float4*)(g_qkv + (size_t)col * 384 + 256))[l];
    float* dst = g_acc + (size_t)row * 128 + (l << 2);
    asm volatile("red.global.add.v4.f32 [%0], {%1,%2,%3,%4};"
                 :: "l"(dst),
                    "f"(ev * vv.x), "f"(ev * vv.y), "f"(ev * vv.z), "f"(ev * vv.w)
                 : "memory");
}

// ---------------------------------------------------------------------------
extern "C" void kernel_launch(void* const* d_in, const int* in_sizes, int n_in,
                              void* d_out, int out_size)
{
    const float* x    = (const float*)d_in[0];
    const void*  ei   = d_in[1];
    const float* dist = (const float*)d_in[2];
    const float* Wq  = (const float*)d_in[3];  const float* bq  = (const float*)d_in[4];
    const float* Wk  = (const float*)d_in[5];  const float* bk  = (const float*)d_in[6];
    const float* Wv  = (const float*)d_in[7];  const float* bv  = (const float*)d_in[8];
    const float* Wo  = (const float*)d_in[9];  const float* bo  = (const float*)d_in[10];
    const float* Wg1 = (const float*)d_in[11]; const float* bg1 = (const float*)d_in[12];
    const float* Wg2 = (const float*)d_in[13]; const float* bg2 = (const float*)d_in[14];

    const int N = in_sizes[0] / 256;
    const int E = in_sizes[2];
    float* out = (float*)d_out;

    void* p_acc = nullptr;
    cudaGetSymbolAddress(&p_acc, g_acc);

    static int attr_done = 0;
    if (!attr_done) {
        cudaFuncSetAttribute(gemm_qkv_tf32,
                             cudaFuncAttributeMaxDynamicSharedMemorySize, GEMM_SMEM_BYTES);
        cudaFuncSetAttribute(gemm_out_tf32,
                             cudaFuncAttributeMaxDynamicSharedMemorySize, GEMM_SMEM_BYTES);
        attr_done = 1;
    }

    detect_idx<<<1, 32>>>(ei, E, N);
    convert_idx<<<(2 * E + 255) / 256, 256>>>(ei, 2 * E);
    zero_bufs<<<((N + ROWPAD) * 32 + 255) / 256, 256>>>(N);

    const int mblocks = (N + 127) / 128;
    gemm_qkv_tf32<<<dim3(3, mblocks), 256, GEMM_SMEM_BYTES>>>(
        x, Wq, Wk, Wv, bq, bk, bv, N);

    geo_kernel<<<(E + 255) / 256, 256>>>(dist, Wg1, bg1, Wg2, bg2, E);
    edge_warp<<<(E + 7) / 8, 256>>>(E);

    gemm_out_tf32<<<dim3(1, mblocks), 256, GEMM_SMEM_BYTES>>>(
        (const float*)p_acc, Wo, bo, N);
    copy_out<<<(N * 32 + 255) / 256, 256>>>(out, N * 32);
}

// round 15
// speedup vs baseline: 1.9138x; 1.0832x over previous
#include <cuda_runtime.h>
#include <mma.h>
#include <cstdint>
#include <cstddef>

using namespace nvcuda;

// Problem-shape capacities (fixed by the dataset)
#define NODES_CAP 50000
#define ROWPAD    128          // tile-overwrite padding
#define EDGES_CAP 800000

// ---------------- device scratch (static: allocation rules) ----------------
__device__ float g_qkv[(size_t)(NODES_CAP + ROWPAD) * 384]; // [N][384] q|k|v fp32 (row-padded)
__device__ float g_geo[(size_t)EDGES_CAP * 8];              // [E][8] geo bias
__device__ float g_s  [(size_t)(NODES_CAP + ROWPAD) * 8];   // [N][8] softmax denom (padded)
__device__ float g_acc[(size_t)NODES_CAP * 128];            // [N][128] UNNORMALIZED attn out
__device__ float g_opad[(size_t)(NODES_CAP + ROWPAD) * 128];// row-padded final out staging
__device__ int   g_idx[(size_t)EDGES_CAP * 2];              // row | col as int32
__device__ int   g_idx64;

// ---------------------------------------------------------------------------
__global__ void detect_idx(const void* __restrict__ ei, int E, int N)
{
    if (blockIdx.x == 0 && threadIdx.x == 0) {
        const long long* p = (const long long*)ei;
        int ok = 1;
        for (int i = 0; i < 64; i++) {
            const long long v = p[i];
            if (v < 0 || v >= (long long)N) { ok = 0; break; }
        }
        g_idx64 = ok;
    }
}

__global__ __launch_bounds__(256) void convert_idx(const void* __restrict__ ei, int total)
{
    const int t = blockIdx.x * 256 + threadIdx.x;
    if (t >= total) return;
    if (g_idx64) g_idx[t] = (int)((const long long*)ei)[t];
    else         g_idx[t] = ((const int*)ei)[t];
}

__global__ __launch_bounds__(256) void zero_bufs(int N)
{
    const int t = blockIdx.x * 256 + threadIdx.x;
    const int n_s   = (N + ROWPAD) * 8 / 4;
    const int n_acc = N * 128 / 4;
    if (t < n_s)   ((float4*)g_s)[t]   = make_float4(0.f, 0.f, 0.f, 0.f);
    if (t < n_acc) ((float4*)g_acc)[t] = make_float4(0.f, 0.f, 0.f, 0.f);
}

// ---------------------------------------------------------------------------
// cp.async double-buffered TF32 GEMM core (NT layout), 2 CTAs/SM.
// C[m, coff+n] = sum_k A[m,k]*B[n,k] + bias[n].
// BM=BN=128, BK=32; 8 warps 2(M)x4(N); warp tile 64x32 = 4x2 wmma m16n16k8.
// SCALE: multiply A rows in smem by 1/(g_s[m][head]+1e-12) (softmax fusion);
// BK=32 covers exactly 2 heads -> thread=(row, 16-col half).
// C is row-padded so full-tile stores past M are safe.
// Dynamic smem: 2 stages x (As 128x36 + Bs 128x36) + bias 16x136.
// ---------------------------------------------------------------------------
#define STAGE_F (128 * 36 * 2)
#define GEMM_SMEM_BYTES ((2 * STAGE_F + 16 * 136) * 4)

template<int K, bool SCALE>
__device__ __forceinline__ void gemm_core(
    const float* __restrict__ A, const float* __restrict__ B,
    const float* __restrict__ bias, float* __restrict__ C,
    int M, int ldc, int coff, int bm0)
{
    extern __shared__ float smem[];
    float* biasS = smem + 2 * STAGE_F;

    const int tid = threadIdx.x;
    const int wid = tid >> 5;
    const int warp_m = wid & 1;
    const int warp_n = wid >> 1;

    for (int t = tid; t < 16 * 128; t += 256)
        biasS[(t >> 7) * 136 + (t & 127)] = bias[t & 127];
    __syncthreads();

    wmma::fragment<wmma::accumulator, 16, 16, 8, float> c[4][2];
#pragma unroll
    for (int i = 0; i < 4; i++)
#pragma unroll
        for (int j = 0; j < 2; j++)
            wmma::load_matrix_sync(c[i][j], &biasS[(warp_n << 5) + (j << 4)], 136,
                                   wmma::mem_row_major);

    constexpr int NT = K / 32;

    auto issue_stage = [&](int kt) {
        float* As = smem + (kt & 1) * STAGE_F;
        float* Bs = As + 128 * 36;
        const int k0 = kt << 5;
#pragma unroll
        for (int l = 0; l < 4; l++) {
            const int idx = tid + (l << 8);
            const int r  = idx >> 3;
            const int c4 = (idx & 7) << 2;
            const int grow = bm0 + r;
            const int ok = grow < M;
            const float* ga = A + (size_t)(ok ? grow : 0) * K + k0 + c4;
            const uint32_t sa = (uint32_t)__cvta_generic_to_shared(As + r * 36 + c4);
            const int sz = ok ? 16 : 0;   // src-size 0 -> zero-fill 16B
            asm volatile("cp.async.cg.shared.global [%0], [%1], 16, %2;"
                         :: "r"(sa), "l"(ga), "r"(sz));
            const float* gb = B + (size_t)r * K + k0 + c4;
            const uint32_t sb = (uint32_t)__cvta_generic_to_shared(Bs + r * 36 + c4);
            asm volatile("cp.async.cg.shared.global [%0], [%1], 16;"
                         :: "r"(sb), "l"(gb));
        }
        asm volatile("cp.async.commit_group;");
    };

    issue_stage(0);

    for (int kt = 0; kt < NT; kt++) {
        asm volatile("cp.async.wait_group 0;");
        __syncthreads();

        if (kt + 1 < NT) issue_stage(kt + 1);

        float* As = smem + (kt & 1) * STAGE_F;
        float* Bs = As + 128 * 36;

        if (SCALE) {
            const int r = tid >> 1;
            const int half = tid & 1;
            const int grow = bm0 + r;
            const float rcp = 1.0f / (g_s[(size_t)grow * 8 + (kt << 1) + half] + 1e-12f);
            float* p = As + r * 36 + (half << 4);
#pragma unroll
            for (int i = 0; i < 16; i++) p[i] *= rcp;
            __syncthreads();
        }

#pragma unroll
        for (int ks = 0; ks < 4; ks++) {
            const int kk = ks << 3;
            wmma::fragment<wmma::matrix_a, 16, 16, 8, wmma::precision::tf32, wmma::row_major> af[4];
            wmma::fragment<wmma::matrix_b, 16, 16, 8, wmma::precision::tf32, wmma::col_major> bf[2];
#pragma unroll
            for (int i = 0; i < 4; i++) {
                wmma::load_matrix_sync(af[i], &As[((warp_m << 6) + (i << 4)) * 36 + kk], 36);
#pragma unroll
                for (int t = 0; t < af[i].num_elements; t++)
                    af[i].x[t] = wmma::__float_to_tf32(af[i].x[t]);
            }
#pragma unroll
            for (int j = 0; j < 2; j++) {
                wmma::load_matrix_sync(bf[j], &Bs[((warp_n << 5) + (j << 4)) * 36 + kk], 36);
#pragma unroll
                for (int t = 0; t < bf[j].num_elements; t++)
                    bf[j].x[t] = wmma::__float_to_tf32(bf[j].x[t]);
            }
#pragma unroll
            for (int i = 0; i < 4; i++)
#pragma unroll
                for (int j = 0; j < 2; j++)
                    wmma::mma_sync(c[i][j], af[i], bf[j], c[i][j]);
        }
    }

#pragma unroll
    for (int i = 0; i < 4; i++) {
        const int m0 = bm0 + (warp_m << 6) + (i << 4);
#pragma unroll
        for (int j = 0; j < 2; j++) {
            const int n0 = coff + (warp_n << 5) + (j << 4);
            wmma::store_matrix_sync(C + (size_t)m0 * ldc + n0, c[i][j], ldc,
                                    wmma::mem_row_major);
        }
    }
}

// Merged QKV: blockIdx.x in {0,1,2} selects (Wq|Wk|Wv). 2 CTAs/SM target.
__global__ __launch_bounds__(256, 2) void gemm_qkv_tf32(
    const float* __restrict__ A,
    const float* __restrict__ Wq, const float* __restrict__ Wk, const float* __restrict__ Wv,
    const float* __restrict__ bq, const float* __restrict__ bk, const float* __restrict__ bv,
    int M)
{
    const float* B    = (blockIdx.x == 0) ? Wq : (blockIdx.x == 1) ? Wk : Wv;
    const float* bias = (blockIdx.x == 0) ? bq : (blockIdx.x == 1) ? bk : bv;
    gemm_core<256, false>(A, B, bias, g_qkv, M, 384, blockIdx.x << 7, blockIdx.y << 7);
}

// Output GEMM: fused softmax normalization, fp32 to padded staging.
__global__ __launch_bounds__(256, 2) void gemm_out_tf32(
    const float* __restrict__ A, const float* __restrict__ B,
    const float* __restrict__ bias, int M)
{
    gemm_core<128, true>(A, B, bias, g_opad, M, 128, 0, blockIdx.y << 7);
}

__global__ __launch_bounds__(256) void copy_out(float* __restrict__ dst, int n4)
{
    const int t = blockIdx.x * 256 + threadIdx.x;
    if (t < n4) ((float4*)dst)[t] = ((const float4*)g_opad)[t];
}

// ---------------------------------------------------------------------------
// Geo bias: dense per-edge MLP, one thread per edge -> g_geo[e][8].
// centers = linspace(0,6,16) = 0.4*i, gamma = 1.
// ---------------------------------------------------------------------------
__global__ __launch_bounds__(256) void geo_kernel(
    const float* __restrict__ dist,
    const float* __restrict__ Wg1, const float* __restrict__ bg1,
    const float* __restrict__ Wg2, const float* __restrict__ bg2,
    int E)
{
    __shared__ float sW1[256], sW2[128], sb1[16], sb2[8];
    const int tid = threadIdx.x;
    sW1[tid] = Wg1[tid];
    if (tid < 128) sW2[tid] = Wg2[tid];
    if (tid < 16)  sb1[tid] = bg1[tid];
    if (tid < 8)   sb2[tid] = bg2[tid];
    __syncthreads();

    const int e = blockIdx.x * 256 + tid;
    if (e >= E) return;

    const float d = dist[e];
    float r[16];
#pragma unroll
    for (int i = 0; i < 16; i++) {
        const float t = d - 0.4f * (float)i;
        r[i] = __expf(-t * t);
    }
    float o[8];
#pragma unroll
    for (int h = 0; h < 8; h++) o[h] = sb2[h];
#pragma unroll
    for (int j = 0; j < 16; j++) {
        float hj = sb1[j];
#pragma unroll
        for (int i = 0; i < 16; i++) hj += r[i] * sW1[j * 16 + i];
        hj = fmaxf(hj, 0.f);
#pragma unroll
        for (int h = 0; h < 8; h++) o[h] += hj * sW2[h * 16 + j];
    }
    float* gp = g_geo + (size_t)e * 8;
    *(float4*)(gp + 0) = make_float4(o[0], o[1], o[2], o[3]);
    *(float4*)(gp + 4) = make_float4(o[4], o[5], o[6], o[7]);
}

// ---------------------------------------------------------------------------
// Warp-per-edge attention pass (fp32, coalesced gathers + red.v4 scatter).
// Lane l owns float4 l of the 128-float node row (head h=l>>2).
// Unnormalized accumulation; softmax 1/s deferred into gemm_out_tf32.
// No segment-max: logits are O(1) here, exp cannot overflow.
// ---------------------------------------------------------------------------
__global__ __launch_bounds__(256) void edge_warp(int E)
{
    const int e = blockIdx.x * 8 + (threadIdx.x >> 5);
    if (e >= E) return;
    const int l = threadIdx.x & 31;
    const int h = l >> 2;

    const int row = g_idx[e];
    const int col = g_idx[E + e];

    const float4 qv = ((const float4*)(g_qkv + (size_t)row * 384))[l];
    const float4 kv = ((const float4*)(g_qkv + (size_t)col * 384 + 128))[l];
    float part = qv.x * kv.x + qv.y * kv.y + qv.z * kv.z + qv.w * kv.w;
    part += __shfl_xor_sync(0xffffffffu, part, 1);
    part += __shfl_xor_sync(0xffffffffu, part, 2);

    const float geo = g_geo[(size_t)e * 8 + h];
    const float ev = __expf(part * 0.25f + geo);

    if ((l & 3) == 0)
        asm volatile("red.global.add.f32 [%0], %1;"
                     :: "l"(&g_s[(size_t)row * 8 + h]), "f"(ev) : "memory");

    const float4 vv = ((const float4*)(g_qkv + (size_t)col * 384 + 256))[l];
    float* dst = g_acc + (size_t)row * 128 + (l << 2);
    asm volatile("red.global.add.v4.f32 [%0], {%1,%2,%3,%4};"
                 :: "l"(dst),
                    "f"(ev * vv.x), "f"(ev * vv.y), "f"(ev * vv.z), "f"(ev * vv.w)
                 : "memory");
}

// ---------------------------------------------------------------------------
extern "C" void kernel_launch(void* const* d_in, const int* in_sizes, int n_in,
                              void* d_out, int out_size)
{
    const float* x    = (const float*)d_in[0];
    const void*  ei   = d_in[1];
    const float* dist = (const float*)d_in[2];
    const float* Wq  = (const float*)d_in[3];  const float* bq  = (const float*)d_in[4];
    const float* Wk  = (const float*)d_in[5];  const float* bk  = (const float*)d_in[6];
    const float* Wv  = (const float*)d_in[7];  const float* bv  = (const float*)d_in[8];
    const float* Wo  = (const float*)d_in[9];  const float* bo  = (const float*)d_in[10];
    const float* Wg1 = (const float*)d_in[11]; const float* bg1 = (const float*)d_in[12];
    const float* Wg2 = (const float*)d_in[13]; const float* bg2 = (const float*)d_in[14];

    const int N = in_sizes[0] / 256;
    const int E = in_sizes[2];
    float* out = (float*)d_out;

    void* p_acc = nullptr;
    cudaGetSymbolAddress(&p_acc, g_acc);

    static int attr_done = 0;
    if (!attr_done) {
        cudaFuncSetAttribute(gemm_qkv_tf32,
                             cudaFuncAttributeMaxDynamicSharedMemorySize, GEMM_SMEM_BYTES);
        cudaFuncSetAttribute(gemm_out_tf32,
                             cudaFuncAttributeMaxDynamicSharedMemorySize, GEMM_SMEM_BYTES);
        attr_done = 1;
    }

    detect_idx<<<1, 32>>>(ei, E, N);
    convert_idx<<<(2 * E + 255) / 256, 256>>>(ei, 2 * E);
    zero_bufs<<<((N + ROWPAD) * 32 + 255) / 256, 256>>>(N);

    const int mblocks = (N + 127) / 128;
    gemm_qkv_tf32<<<dim3(3, mblocks), 256, GEMM_SMEM_BYTES>>>(
        x, Wq, Wk, Wv, bq, bk, bv, N);

    geo_kernel<<<(E + 255) / 256, 256>>>(dist, Wg1, bg1, Wg2, bg2, E);
    edge_warp<<<(E + 7) / 8, 256>>>(E);

    gemm_out_tf32<<<dim3(1, mblocks), 256, GEMM_SMEM_BYTES>>>(
        (const float*)p_acc, Wo, bo, N);
    copy_out<<<(N * 32 + 255) / 256, 256>>>(out, N * 32);
}